// round 13
// baseline (speedup 1.0000x reference)
#include <cuda_runtime.h>
#include <math.h>

#define BB 4
#define NN 20000
#define EE 16
#define CC 128
#define BN (BB*NN)

#define THREADS 1024
#define TILE 128
#define NTILES (BN / TILE)     // 625
#define GRID 148
#define US 68                  // us row stride in u32 (conflict-free frag LDS)

typedef unsigned long long u64;
typedef unsigned int u32;

// Scratch (+1 zero pad row at index BN for -1 edges)
__device__ float g_isd[BN];
__device__ float g_bufA[((size_t)BN + 1) * CC];
__device__ float g_bufB[((size_t)BN + 1) * CC];
// bf16 B fragments: [layer][ks(8)][nb(16)][lane(32)] uint2 (b0,b1), hi and lo
__device__ uint2 g_Wfh[3 * 8 * 16 * 32];
__device__ uint2 g_Wfl[3 * 8 * 16 * 32];

union F4 { float4 v; u64 p[2]; float f[4]; };

__device__ __forceinline__ u64 add2(u64 a, u64 b) {
    u64 d; asm("add.rn.f32x2 %0,%1,%2;" : "=l"(d) : "l"(a), "l"(b)); return d;
}
__device__ __forceinline__ u64 mul2(u64 a, u64 b) {
    u64 d; asm("mul.rn.f32x2 %0,%1,%2;" : "=l"(d) : "l"(a), "l"(b)); return d;
}
__device__ __forceinline__ u64 dup2(float s) {
    u64 d; asm("mov.b64 %0,{%1,%1};" : "=l"(d) : "f"(s)); return d;
}
// pack two f32 -> bf16x2 (lo_val -> bits[15:0], hi_val -> bits[31:16])
__device__ __forceinline__ u32 packbf(float lo_val, float hi_val) {
    u32 d; asm("cvt.rn.bf16x2.f32 %0, %1, %2;" : "=r"(d) : "f"(hi_val), "f"(lo_val));
    return d;
}
__device__ __forceinline__ u32 smem_u32(const void* p) {
    u32 a;
    asm("{ .reg .u64 t; cvta.to.shared.u64 t, %1; cvt.u32.u64 %0, t; }" : "=r"(a) : "l"(p));
    return a;
}
__device__ __forceinline__ float elu(float v) { return v > 0.0f ? v : expm1f(v); }

// D(16x8,f32) += A(16x16,bf16,row) * B(16x8,bf16,col)
__device__ __forceinline__ void mma16(float* c, const u32* a, u32 b0, u32 b1) {
    asm("mma.sync.aligned.m16n8k16.row.col.f32.bf16.bf16.f32 "
        "{%0,%1,%2,%3}, {%4,%5,%6,%7}, {%8,%9}, {%0,%1,%2,%3};"
        : "+f"(c[0]), "+f"(c[1]), "+f"(c[2]), "+f"(c[3])
        : "r"(a[0]), "r"(a[1]), "r"(a[2]), "r"(a[3]), "r"(b0), "r"(b1));
}

#define BAR_SYNC(id)   asm volatile("bar.sync %0, %1;"   :: "r"(id), "r"(THREADS) : "memory")
#define BAR_ARRIVE(id) asm volatile("bar.arrive %0, %1;" :: "r"(id), "r"(THREADS) : "memory")

// ---- prep kernels ----
__global__ void isd_kernel(const int* __restrict__ edge) {
    int g = blockIdx.x * blockDim.x + threadIdx.x;
    if (g >= BN) return;
    const int* e = edge + (size_t)g * EE;
    int d = 1;
#pragma unroll
    for (int i = 0; i < EE; i++) d += (e[i] >= 0);
    g_isd[g] = rsqrtf((float)d);
}

__global__ void zprep_kernel(const float* __restrict__ x) {
    int t = blockIdx.x * blockDim.x + threadIdx.x;
    if (t < BN * (CC / 4)) {
        int row = t >> 5;
        float s = g_isd[row];
        F4 v; v.v = *(const float4*)(x + (size_t)t * 4);
        u64 sd = dup2(s);
        v.p[0] = mul2(v.p[0], sd);
        v.p[1] = mul2(v.p[1], sd);
        *(float4*)(g_bufA + (size_t)t * 4) = v.v;
    } else {
        int r = t - BN * (CC / 4);
        if (r < CC / 4) {
            *(float4*)(g_bufA + (size_t)BN * CC + r * 4) = make_float4(0, 0, 0, 0);
            *(float4*)(g_bufB + (size_t)BN * CC + r * 4) = make_float4(0, 0, 0, 0);
        }
    }
}

// Pack W into bf16 m16n8k16 B-fragments, hi/lo split.
// Block (ks, nb): k in [16ks,16ks+16), n in [8nb,8nb+8). B[k][n] = W[n][k].
// lane: gid=lane>>2 (n), tid=lane&3.
// b0 = {B[2tid][n] lo, B[2tid+1][n] hi}; b1 = same with k+8.
__global__ void wfrag_kernel(const float* __restrict__ W0,
                             const float* __restrict__ W1,
                             const float* __restrict__ W2) {
    int t = blockIdx.x * blockDim.x + threadIdx.x;
    if (t >= 3 * 8 * 16 * 32) return;
    int lane = t & 31;
    int nb   = (t >> 5) & 15;
    int ks   = (t >> 9) & 7;
    int l    = t >> 12;
    int gid = lane >> 2, tid = lane & 3;
    const float* W = (l == 0) ? W0 : (l == 1) ? W1 : W2;
    const int n = 8 * nb + gid, k0 = 16 * ks;

    float w00 = W[n * CC + k0 + 2 * tid];
    float w01 = W[n * CC + k0 + 2 * tid + 1];
    float w10 = W[n * CC + k0 + 8 + 2 * tid];
    float w11 = W[n * CC + k0 + 8 + 2 * tid + 1];

    u32 h0 = packbf(w00, w01);
    u32 h1 = packbf(w10, w11);
    float h00 = __uint_as_float(h0 << 16), h01 = __uint_as_float(h0 & 0xFFFF0000u);
    float h10 = __uint_as_float(h1 << 16), h11 = __uint_as_float(h1 & 0xFFFF0000u);
    u32 l0 = packbf(w00 - h00, w01 - h01);
    u32 l1 = packbf(w10 - h10, w11 - h11);

    g_Wfh[t] = make_uint2(h0, h1);
    g_Wfl[t] = make_uint2(l0, l1);
}

// ---- fused layer: producers gather+split -> us hi/lo; consumers bf16 mma ----
template<bool LAST>
__global__ __launch_bounds__(THREADS, 1)
void layer_kernel(const float* __restrict__ zin,
                  const int*   __restrict__ edge,
                  const uint2* __restrict__ Wfh,
                  const uint2* __restrict__ Wfl,
                  float*       __restrict__ out)
{
    extern __shared__ float sm[];
    uint2* Wfh_s = (uint2*)sm;                      // 4096 uint2 = 32 KB
    uint2* Wfl_s = Wfh_s + 8 * 16 * 32;             // 32 KB
    u32*   ushi  = (u32*)(Wfl_s + 8 * 16 * 32);     // [2][128][US]
    u32*   uslo  = ushi + 2 * TILE * US;            // [2][128][US]
    float* isd_s = (float*)(uslo + 2 * TILE * US);  // [2][128]

    const int t = threadIdx.x, w = t >> 5, lane = t & 31;
    const int gid = lane >> 2, tid = lane & 3;

    // Stage W fragments once (cp.async). 32 KB per array = 2048 x 16B chunks.
    {
        const u32 dh = smem_u32(Wfh_s), dl = smem_u32(Wfl_s);
#pragma unroll
        for (int i = 0; i < 2048 / THREADS; i++) {
            int idx = t + i * THREADS;
            asm volatile("cp.async.ca.shared.global [%0], [%1], 16;"
                         :: "r"(dh + idx * 16), "l"((const char*)Wfh + idx * 16));
            asm volatile("cp.async.ca.shared.global [%0], [%1], 16;"
                         :: "r"(dl + idx * 16), "l"((const char*)Wfl + idx * 16));
        }
        asm volatile("cp.async.commit_group;");
        asm volatile("cp.async.wait_group 0;" ::: "memory");
    }
    __syncthreads();

    if (w < 16) {
        // ------------- producer: gather 8 nodes/tile (2 halves of 4) ---------
        int it = 0;
        for (int tile = blockIdx.x; tile < NTILES; tile += GRID, it++) {
            const int buf = it & 1;
            u32* uh = ushi + buf * (TILE * US);
            u32* ul = uslo + buf * (TILE * US);
            const int node0 = tile * TILE;

            if (it >= 2) BAR_SYNC(3 + buf);          // wait buffer empty

#pragma unroll
            for (int h = 0; h < 2; h++) {
                F4    acc[4];
                int   eidx[4];
                float sn[4];
                const int gbase = node0 + w * 8 + h * 4;
#pragma unroll
                for (int i = 0; i < 4; i++) {
                    const int gn = gbase + i;
                    sn[i] = g_isd[gn];
                    int m = -1;
                    if (lane < EE) m = edge[(size_t)gn * EE + lane];
                    eidx[i] = (m < 0) ? BN : ((gn / NN) * NN + m);
                    acc[i].v = *((const float4*)(zin + (size_t)gn * CC) + lane);
                }
#pragma unroll 4
                for (int e = 0; e < EE; e++) {
#pragma unroll
                    for (int i = 0; i < 4; i++) {
                        int m = __shfl_sync(0xffffffffu, eidx[i], e);
                        F4 v; v.v = *((const float4*)(zin + (size_t)m * CC) + lane);
                        acc[i].p[0] = add2(acc[i].p[0], v.p[0]);
                        acc[i].p[1] = add2(acc[i].p[1], v.p[1]);
                    }
                }
#pragma unroll
                for (int i = 0; i < 4; i++) {
                    u64 sd = dup2(sn[i]);
                    acc[i].p[0] = mul2(acc[i].p[0], sd);
                    acc[i].p[1] = mul2(acc[i].p[1], sd);
                    // split into bf16 hi/lo pairs: pair0=(f0,f1), pair1=(f2,f3)
                    u32 hp0 = packbf(acc[i].f[0], acc[i].f[1]);
                    u32 hp1 = packbf(acc[i].f[2], acc[i].f[3]);
                    float h00 = __uint_as_float(hp0 << 16);
                    float h01 = __uint_as_float(hp0 & 0xFFFF0000u);
                    float h10 = __uint_as_float(hp1 << 16);
                    float h11 = __uint_as_float(hp1 & 0xFFFF0000u);
                    u32 lp0 = packbf(acc[i].f[0] - h00, acc[i].f[1] - h01);
                    u32 lp1 = packbf(acc[i].f[2] - h10, acc[i].f[3] - h11);
                    const int row = w * 8 + h * 4 + i;
                    *(uint2*)(uh + row * US + 2 * lane) = make_uint2(hp0, hp1);
                    *(uint2*)(ul + row * US + 2 * lane) = make_uint2(lp0, lp1);
                }
            }
            if (lane < 8) isd_s[buf * TILE + w * 8 + lane] = g_isd[node0 + w * 8 + lane];

            BAR_ARRIVE(1 + buf);                     // signal buffer full
        }
    } else {
        // ------------- consumer: 32x32 mma tile + epilogue -------------------
        const int cw = w - 16, wm = cw & 3, wn = cw >> 2;   // 4x4 grid, 32x32 tiles
        const int m0 = wm * 32;

        int it = 0;
        for (int tile = blockIdx.x; tile < NTILES; tile += GRID, it++) {
            const int buf = it & 1;
            const u32* uh = ushi + buf * (TILE * US);
            const u32* ul = uslo + buf * (TILE * US);
            const int node0 = tile * TILE;

            BAR_SYNC(1 + buf);                       // wait buffer full

            float acc[2][4][4];
#pragma unroll
            for (int f = 0; f < 2; f++)
#pragma unroll
                for (int g = 0; g < 4; g++)
#pragma unroll
                    for (int j = 0; j < 4; j++) acc[f][g][j] = 0.0f;

            for (int ks = 0; ks < 8; ks++) {
                u32 ah[2][4], al[2][4];
#pragma unroll
                for (int f = 0; f < 2; f++) {
                    const int r = m0 + 16 * f + gid;
                    const int c = ks * 8 + tid;
                    ah[f][0] = uh[r * US + c];
                    ah[f][1] = uh[(r + 8) * US + c];
                    ah[f][2] = uh[r * US + c + 4];
                    ah[f][3] = uh[(r + 8) * US + c + 4];
                    al[f][0] = ul[r * US + c];
                    al[f][1] = ul[(r + 8) * US + c];
                    al[f][2] = ul[r * US + c + 4];
                    al[f][3] = ul[(r + 8) * US + c + 4];
                }
#pragma unroll
                for (int g = 0; g < 4; g++) {
                    const int nb = wn * 4 + g;
                    uint2 bh = Wfh_s[(ks * 16 + nb) * 32 + lane];
                    uint2 bl = Wfl_s[(ks * 16 + nb) * 32 + lane];
#pragma unroll
                    for (int f = 0; f < 2; f++) {
                        mma16(acc[f][g], ah[f], bh.x, bh.y);
                        mma16(acc[f][g], al[f], bh.x, bh.y);
                        mma16(acc[f][g], ah[f], bl.x, bl.y);
                    }
                }
            }

            float s[2][2];
#pragma unroll
            for (int f = 0; f < 2; f++) {
                s[f][0] = isd_s[buf * TILE + m0 + 16 * f + gid];
                s[f][1] = isd_s[buf * TILE + m0 + 16 * f + gid + 8];
            }

            BAR_ARRIVE(3 + buf);                     // buffer free for producer

#pragma unroll
            for (int f = 0; f < 2; f++) {
                const int r0 = m0 + 16 * f + gid;
#pragma unroll
                for (int g = 0; g < 4; g++) {
                    const int c = wn * 32 + g * 8 + 2 * tid;
                    float2 v0, v1;
                    v0.x = elu(acc[f][g][0]); v0.y = elu(acc[f][g][1]);
                    v1.x = elu(acc[f][g][2]); v1.y = elu(acc[f][g][3]);
                    if (!LAST) {
                        v0.x *= s[f][0]; v0.y *= s[f][0];
                        v1.x *= s[f][1]; v1.y *= s[f][1];
                    }
                    *(float2*)(out + (size_t)(node0 + r0) * CC + c) = v0;
                    *(float2*)(out + (size_t)(node0 + r0 + 8) * CC + c) = v1;
                }
            }
        }
    }
}

extern "C" void kernel_launch(void* const* d_in, const int* in_sizes, int n_in,
                              void* d_out, int out_size) {
    const float* x    = (const float*)d_in[0];
    const int*   edge = (const int*)d_in[1];
    const float* W0   = (const float*)d_in[2];
    const float* W1   = (const float*)d_in[3];
    const float* W2   = (const float*)d_in[4];
    float* out = (float*)d_out;

    float *bufA = nullptr, *bufB = nullptr;
    uint2 *Wfh = nullptr, *Wfl = nullptr;
    cudaGetSymbolAddress((void**)&bufA, g_bufA);
    cudaGetSymbolAddress((void**)&bufB, g_bufB);
    cudaGetSymbolAddress((void**)&Wfh,  g_Wfh);
    cudaGetSymbolAddress((void**)&Wfl,  g_Wfl);

    const int smem_bytes =
        2 * 8 * 16 * 32 * 8 +            // W frags (hi+lo) 64 KB
        2 * 2 * TILE * US * 4 +          // us hi/lo double-buffered ~136 KB
        2 * TILE * 4;                    // isd
    cudaFuncSetAttribute(layer_kernel<false>,
                         cudaFuncAttributeMaxDynamicSharedMemorySize, smem_bytes);
    cudaFuncSetAttribute(layer_kernel<true>,
                         cudaFuncAttributeMaxDynamicSharedMemorySize, smem_bytes);

    isd_kernel<<<(BN + 255) / 256, 256>>>(edge);

    const int zthreads = BN * (CC / 4) + (CC / 4);
    zprep_kernel<<<(zthreads + 255) / 256, 256>>>(x);

    wfrag_kernel<<<(3 * 8 * 16 * 32 + 255) / 256, 256>>>(W0, W1, W2);

    const int FS = 8 * 16 * 32;   // frags per layer
    layer_kernel<false><<<GRID, THREADS, smem_bytes>>>(bufA, edge, Wfh + 0 * FS, Wfl + 0 * FS, bufB);
    layer_kernel<false><<<GRID, THREADS, smem_bytes>>>(bufB, edge, Wfh + 1 * FS, Wfl + 1 * FS, bufA);
    layer_kernel<true ><<<GRID, THREADS, smem_bytes>>>(bufA, edge, Wfh + 2 * FS, Wfl + 2 * FS, out);
}

// round 14
// speedup vs baseline: 1.1300x; 1.1300x over previous
#include <cuda_runtime.h>
#include <math.h>

#define BB 4
#define NN 20000
#define EE 16
#define CC 128
#define BN (BB*NN)

#define THREADS 1024
#define TILE 64
#define NTILES (BN / TILE)     // 1250
#define GRID 148
#define US 68                  // us row stride in u32 (conflict-free frag LDS)

typedef unsigned long long u64;
typedef unsigned int u32;

// Scratch (+1 zero pad row at index BN for -1 edges)
__device__ float g_isd[BN];
__device__ float g_bufA[((size_t)BN + 1) * CC];
__device__ float g_bufB[((size_t)BN + 1) * CC];
// bf16 B fragments: [layer][ks(8)][nb(16)][lane(32)] uint2 (b0,b1), hi and lo
__device__ uint2 g_Wfh[3 * 8 * 16 * 32];
__device__ uint2 g_Wfl[3 * 8 * 16 * 32];

union F4 { float4 v; u64 p[2]; float f[4]; };

__device__ __forceinline__ u64 add2(u64 a, u64 b) {
    u64 d; asm("add.rn.f32x2 %0,%1,%2;" : "=l"(d) : "l"(a), "l"(b)); return d;
}
__device__ __forceinline__ u64 mul2(u64 a, u64 b) {
    u64 d; asm("mul.rn.f32x2 %0,%1,%2;" : "=l"(d) : "l"(a), "l"(b)); return d;
}
__device__ __forceinline__ u64 dup2(float s) {
    u64 d; asm("mov.b64 %0,{%1,%1};" : "=l"(d) : "f"(s)); return d;
}
// pack two f32 -> bf16x2 (lo_val -> bits[15:0], hi_val -> bits[31:16])
__device__ __forceinline__ u32 packbf(float lo_val, float hi_val) {
    u32 d; asm("cvt.rn.bf16x2.f32 %0, %1, %2;" : "=r"(d) : "f"(hi_val), "f"(lo_val));
    return d;
}
__device__ __forceinline__ u32 smem_u32(const void* p) {
    u32 a;
    asm("{ .reg .u64 t; cvta.to.shared.u64 t, %1; cvt.u32.u64 %0, t; }" : "=r"(a) : "l"(p));
    return a;
}
__device__ __forceinline__ float elu(float v) { return v > 0.0f ? v : expm1f(v); }

// D(16x8,f32) += A(16x16,bf16,row) * B(16x8,bf16,col)
__device__ __forceinline__ void mma16(float* c, const u32* a, u32 b0, u32 b1) {
    asm("mma.sync.aligned.m16n8k16.row.col.f32.bf16.bf16.f32 "
        "{%0,%1,%2,%3}, {%4,%5,%6,%7}, {%8,%9}, {%0,%1,%2,%3};"
        : "+f"(c[0]), "+f"(c[1]), "+f"(c[2]), "+f"(c[3])
        : "r"(a[0]), "r"(a[1]), "r"(a[2]), "r"(a[3]), "r"(b0), "r"(b1));
}

#define BAR_SYNC(id)   asm volatile("bar.sync %0, %1;"   :: "r"(id), "r"(THREADS) : "memory")
#define BAR_ARRIVE(id) asm volatile("bar.arrive %0, %1;" :: "r"(id), "r"(THREADS) : "memory")

// ---- prep kernels ----
__global__ void isd_kernel(const int* __restrict__ edge) {
    int g = blockIdx.x * blockDim.x + threadIdx.x;
    if (g >= BN) return;
    const int* e = edge + (size_t)g * EE;
    int d = 1;
#pragma unroll
    for (int i = 0; i < EE; i++) d += (e[i] >= 0);
    g_isd[g] = rsqrtf((float)d);
}

__global__ void zprep_kernel(const float* __restrict__ x) {
    int t = blockIdx.x * blockDim.x + threadIdx.x;
    if (t < BN * (CC / 4)) {
        int row = t >> 5;
        float s = g_isd[row];
        F4 v; v.v = *(const float4*)(x + (size_t)t * 4);
        u64 sd = dup2(s);
        v.p[0] = mul2(v.p[0], sd);
        v.p[1] = mul2(v.p[1], sd);
        *(float4*)(g_bufA + (size_t)t * 4) = v.v;
    } else {
        int r = t - BN * (CC / 4);
        if (r < CC / 4) {
            *(float4*)(g_bufA + (size_t)BN * CC + r * 4) = make_float4(0, 0, 0, 0);
            *(float4*)(g_bufB + (size_t)BN * CC + r * 4) = make_float4(0, 0, 0, 0);
        }
    }
}

// Pack W into bf16 m16n8k16 B-fragments, hi/lo split.
// Block (ks, nb): k in [16ks,16ks+16), n in [8nb,8nb+8). B[k][n] = W[n][k].
// lane: gid=lane>>2 (n), tid=lane&3.
// b0 = {B[2tid][n], B[2tid+1][n]}; b1 = same with k+8.
__global__ void wfrag_kernel(const float* __restrict__ W0,
                             const float* __restrict__ W1,
                             const float* __restrict__ W2) {
    int t = blockIdx.x * blockDim.x + threadIdx.x;
    if (t >= 3 * 8 * 16 * 32) return;
    int lane = t & 31;
    int nb   = (t >> 5) & 15;
    int ks   = (t >> 9) & 7;
    int l    = t >> 12;
    int gid = lane >> 2, tid = lane & 3;
    const float* W = (l == 0) ? W0 : (l == 1) ? W1 : W2;
    const int n = 8 * nb + gid, k0 = 16 * ks;

    float w00 = W[n * CC + k0 + 2 * tid];
    float w01 = W[n * CC + k0 + 2 * tid + 1];
    float w10 = W[n * CC + k0 + 8 + 2 * tid];
    float w11 = W[n * CC + k0 + 8 + 2 * tid + 1];

    u32 h0 = packbf(w00, w01);
    u32 h1 = packbf(w10, w11);
    float h00 = __uint_as_float(h0 << 16), h01 = __uint_as_float(h0 & 0xFFFF0000u);
    float h10 = __uint_as_float(h1 << 16), h11 = __uint_as_float(h1 & 0xFFFF0000u);
    u32 l0 = packbf(w00 - h00, w01 - h01);
    u32 l1 = packbf(w10 - h10, w11 - h11);

    g_Wfh[t] = make_uint2(h0, h1);
    g_Wfl[t] = make_uint2(l0, l1);
}

// ---- fused layer: producers gather+split -> us hi/lo; consumers bf16 mma ----
template<bool LAST>
__global__ __launch_bounds__(THREADS, 1)
void layer_kernel(const float* __restrict__ zin,
                  const int*   __restrict__ edge,
                  const uint2* __restrict__ Wfh,
                  const uint2* __restrict__ Wfl,
                  float*       __restrict__ out)
{
    extern __shared__ float sm[];
    uint2* Wfh_s = (uint2*)sm;                      // 4096 uint2 = 32 KB
    uint2* Wfl_s = Wfh_s + 8 * 16 * 32;             // 32 KB
    u32*   ushi  = (u32*)(Wfl_s + 8 * 16 * 32);     // [2][64][US]
    u32*   uslo  = ushi + 2 * TILE * US;            // [2][64][US]
    float* isd_s = (float*)(uslo + 2 * TILE * US);  // [2][64]

    const int t = threadIdx.x, w = t >> 5, lane = t & 31;
    const int gid = lane >> 2, tid = lane & 3;

    // Stage W fragments once (cp.async). 32 KB per array = 2048 x 16B chunks.
    {
        const u32 dh = smem_u32(Wfh_s), dl = smem_u32(Wfl_s);
#pragma unroll
        for (int i = 0; i < 2048 / THREADS; i++) {
            int idx = t + i * THREADS;
            asm volatile("cp.async.ca.shared.global [%0], [%1], 16;"
                         :: "r"(dh + idx * 16), "l"((const char*)Wfh + idx * 16));
            asm volatile("cp.async.ca.shared.global [%0], [%1], 16;"
                         :: "r"(dl + idx * 16), "l"((const char*)Wfl + idx * 16));
        }
        asm volatile("cp.async.commit_group;");
        asm volatile("cp.async.wait_group 0;" ::: "memory");
    }
    __syncthreads();

    if (w < 16) {
        // ------------- producer: gather 4 nodes per tile ---------------------
        int it = 0;
        for (int tile = blockIdx.x; tile < NTILES; tile += GRID, it++) {
            const int buf = it & 1;
            u32* uh = ushi + buf * (TILE * US);
            u32* ul = uslo + buf * (TILE * US);
            const int node0 = tile * TILE;

            if (it >= 2) BAR_SYNC(3 + buf);          // wait buffer empty

            F4    acc[4];
            int   eidx[4];
            float sn[4];
#pragma unroll
            for (int i = 0; i < 4; i++) {
                const int gn = node0 + w * 4 + i;
                sn[i] = g_isd[gn];
                int m = -1;
                if (lane < EE) m = edge[(size_t)gn * EE + lane];
                eidx[i] = (m < 0) ? BN : ((gn / NN) * NN + m);
                acc[i].v = *((const float4*)(zin + (size_t)gn * CC) + lane);
            }
#pragma unroll 4
            for (int e = 0; e < EE; e++) {
#pragma unroll
                for (int i = 0; i < 4; i++) {
                    int m = __shfl_sync(0xffffffffu, eidx[i], e);
                    F4 v; v.v = *((const float4*)(zin + (size_t)m * CC) + lane);
                    acc[i].p[0] = add2(acc[i].p[0], v.p[0]);
                    acc[i].p[1] = add2(acc[i].p[1], v.p[1]);
                }
            }
#pragma unroll
            for (int i = 0; i < 4; i++) {
                u64 sd = dup2(sn[i]);
                acc[i].p[0] = mul2(acc[i].p[0], sd);
                acc[i].p[1] = mul2(acc[i].p[1], sd);
                // split into bf16 hi/lo pairs
                u32 hp0 = packbf(acc[i].f[0], acc[i].f[1]);
                u32 hp1 = packbf(acc[i].f[2], acc[i].f[3]);
                float h00 = __uint_as_float(hp0 << 16);
                float h01 = __uint_as_float(hp0 & 0xFFFF0000u);
                float h10 = __uint_as_float(hp1 << 16);
                float h11 = __uint_as_float(hp1 & 0xFFFF0000u);
                u32 lp0 = packbf(acc[i].f[0] - h00, acc[i].f[1] - h01);
                u32 lp1 = packbf(acc[i].f[2] - h10, acc[i].f[3] - h11);
                const int row = w * 4 + i;
                *(uint2*)(uh + row * US + 2 * lane) = make_uint2(hp0, hp1);
                *(uint2*)(ul + row * US + 2 * lane) = make_uint2(lp0, lp1);
            }
            if (lane < 4) isd_s[buf * TILE + w * 4 + lane] = g_isd[node0 + w * 4 + lane];

            BAR_ARRIVE(1 + buf);                     // signal buffer full
        }
    } else {
        // ------------- consumer: 16x32 mma tile + epilogue -------------------
        const int cw = w - 16, wm = cw & 3, wn = cw >> 2;   // 4x4 grid over 64x128
        const int m0 = wm * 16;

        int it = 0;
        for (int tile = blockIdx.x; tile < NTILES; tile += GRID, it++) {
            const int buf = it & 1;
            const u32* uh = ushi + buf * (TILE * US);
            const u32* ul = uslo + buf * (TILE * US);
            const int node0 = tile * TILE;

            BAR_SYNC(1 + buf);                       // wait buffer full

            float acc[4][4];
#pragma unroll
            for (int g = 0; g < 4; g++)
#pragma unroll
                for (int j = 0; j < 4; j++) acc[g][j] = 0.0f;

            for (int ks = 0; ks < 8; ks++) {
                u32 ah[4], al[4];
                {
                    const int r = m0 + gid;
                    const int c = ks * 8 + tid;
                    ah[0] = uh[r * US + c];
                    ah[1] = uh[(r + 8) * US + c];
                    ah[2] = uh[r * US + c + 4];
                    ah[3] = uh[(r + 8) * US + c + 4];
                    al[0] = ul[r * US + c];
                    al[1] = ul[(r + 8) * US + c];
                    al[2] = ul[r * US + c + 4];
                    al[3] = ul[(r + 8) * US + c + 4];
                }
#pragma unroll
                for (int g = 0; g < 4; g++) {
                    const int nb = wn * 4 + g;
                    uint2 bh = Wfh_s[(ks * 16 + nb) * 32 + lane];
                    uint2 bl = Wfl_s[(ks * 16 + nb) * 32 + lane];
                    mma16(acc[g], ah, bh.x, bh.y);
                    mma16(acc[g], al, bh.x, bh.y);
                    mma16(acc[g], ah, bl.x, bl.y);
                }
            }

            const int r0 = m0 + gid;
            float s0 = isd_s[buf * TILE + r0];
            float s1 = isd_s[buf * TILE + r0 + 8];

            BAR_ARRIVE(3 + buf);                     // buffer free for producer

#pragma unroll
            for (int g = 0; g < 4; g++) {
                const int c = wn * 32 + g * 8 + 2 * tid;
                float2 v0, v1;
                v0.x = elu(acc[g][0]); v0.y = elu(acc[g][1]);
                v1.x = elu(acc[g][2]); v1.y = elu(acc[g][3]);
                if (!LAST) {
                    v0.x *= s0; v0.y *= s0;
                    v1.x *= s1; v1.y *= s1;
                }
                *(float2*)(out + (size_t)(node0 + r0) * CC + c) = v0;
                *(float2*)(out + (size_t)(node0 + r0 + 8) * CC + c) = v1;
            }
        }
    }
}

extern "C" void kernel_launch(void* const* d_in, const int* in_sizes, int n_in,
                              void* d_out, int out_size) {
    const float* x    = (const float*)d_in[0];
    const int*   edge = (const int*)d_in[1];
    const float* W0   = (const float*)d_in[2];
    const float* W1   = (const float*)d_in[3];
    const float* W2   = (const float*)d_in[4];
    float* out = (float*)d_out;

    float *bufA = nullptr, *bufB = nullptr;
    uint2 *Wfh = nullptr, *Wfl = nullptr;
    cudaGetSymbolAddress((void**)&bufA, g_bufA);
    cudaGetSymbolAddress((void**)&bufB, g_bufB);
    cudaGetSymbolAddress((void**)&Wfh,  g_Wfh);
    cudaGetSymbolAddress((void**)&Wfl,  g_Wfl);

    const int smem_bytes =
        2 * 8 * 16 * 32 * 8 +            // W frags (hi+lo) 64 KB
        2 * 2 * TILE * US * 4 +          // us hi/lo double-buffered ~68 KB
        2 * TILE * 4;                    // isd
    cudaFuncSetAttribute(layer_kernel<false>,
                         cudaFuncAttributeMaxDynamicSharedMemorySize, smem_bytes);
    cudaFuncSetAttribute(layer_kernel<true>,
                         cudaFuncAttributeMaxDynamicSharedMemorySize, smem_bytes);

    isd_kernel<<<(BN + 255) / 256, 256>>>(edge);

    const int zthreads = BN * (CC / 4) + (CC / 4);
    zprep_kernel<<<(zthreads + 255) / 256, 256>>>(x);

    wfrag_kernel<<<(3 * 8 * 16 * 32 + 255) / 256, 256>>>(W0, W1, W2);

    const int FS = 8 * 16 * 32;   // frags per layer
    layer_kernel<false><<<GRID, THREADS, smem_bytes>>>(bufA, edge, Wfh + 0 * FS, Wfl + 0 * FS, bufB);
    layer_kernel<false><<<GRID, THREADS, smem_bytes>>>(bufB, edge, Wfh + 1 * FS, Wfl + 1 * FS, bufA);
    layer_kernel<true ><<<GRID, THREADS, smem_bytes>>>(bufA, edge, Wfh + 2 * FS, Wfl + 2 * FS, out);
}